// round 14
// baseline (speedup 1.0000x reference)
#include <cuda_runtime.h>
#include <cuda_fp16.h>
#include <cstdint>

// ---------------------------------------------------------------------------
// KAN-Mixer token-mixing block, fused feature-expansion GEMMs (fp16 mma.sync).
// R12: BK=64 (half the barriers), stage2 N 224->208, stage1 Vs in fp16.
// 512 threads / 16 warps per CTA.
//   stage1: f1 = [rbf(v) (1568), silu(v) (196)]  -> h1[r, 384]   (fp16)
//   stage2: f2 = [rbf(h1) (3072), silu(h1)(384)] -> out[b,p,c] = .. + x[b,p,c]
// ---------------------------------------------------------------------------

#define DINL __device__ __forceinline__

// ---------------- static scratch (no allocations allowed) -------------------
__device__ __align__(16) __half g_W1[1792 * 384];   // [k][o]
__device__ __align__(16) __half g_W2[3456 * 208];   // [k][o] (o padded 196->208)
__device__ __align__(16) __half g_H1[(size_t)49152 * 384];

// ---------------- tiling constants -------------------------------------------
constexpr int BM = 128;
constexpr int BK = 64;
constexpr int NT = 512;                         // threads per CTA

// stage1 (full N=384 per CTA)
constexpr int S1_DIN = 196, S1_KS = 1568, S1_NK = 28, S1_DOUT = 384;
constexpr int S1_RVH = 197;                     // halves per Vs row (odd-ish stride)
constexpr int S1_ROWA = 144;                    // bytes per A row (128 + 16 pad)
constexpr int S1_ROWB = 784;                    // bytes per B row (768 + 16 pad)
constexpr int S1_OFF_A0 = BM * S1_RVH * 2;              // 50432
constexpr int S1_OFF_A1 = S1_OFF_A0 + BM * S1_ROWA;     // 68864
constexpr int S1_OFF_B0 = S1_OFF_A1 + BM * S1_ROWA;     // 87296
constexpr int S1_OFF_B1 = S1_OFF_B0 + BK * S1_ROWB;     // 137472
constexpr int S1_SMEM   = S1_OFF_B1 + BK * S1_ROWB;     // 187648

// stage2 (N = 208, 196 valid)
constexpr int S2_DIN = 384, S2_KS = 3072, S2_NK = 54, S2_NP = 208;
constexpr int S2_RVH = 392;                     // halves per Vs row (16B aligned)
constexpr int S2_ROWA = 144;
constexpr int S2_ROWB = 432;                    // bytes per B row (416 + 16 pad)
constexpr int S2_OFF_A0 = BM * S2_RVH * 2;              // 100352
constexpr int S2_OFF_A1 = S2_OFF_A0 + BM * S2_ROWA;     // 118784
constexpr int S2_OFF_B0 = S2_OFF_A1 + BM * S2_ROWA;     // 137216
constexpr int S2_OFF_B1 = S2_OFF_B0 + BK * S2_ROWB;     // 164864
constexpr int S2_SMEM   = S2_OFF_B1 + BK * S2_ROWB;     // 192512

// ---------------- small helpers ---------------------------------------------
DINL uint32_t smem_u32(const void* p) {
    return (uint32_t)__cvta_generic_to_shared(p);
}

DINL void ldmA(uint32_t (&a)[4], uint32_t addr) {
    asm volatile("ldmatrix.sync.aligned.m8n8.x4.shared.b16 {%0,%1,%2,%3}, [%4];\n"
                 : "=r"(a[0]), "=r"(a[1]), "=r"(a[2]), "=r"(a[3]) : "r"(addr));
}
DINL void ldmBT(uint32_t (&b)[4], uint32_t addr) {
    asm volatile("ldmatrix.sync.aligned.m8n8.x4.trans.shared.b16 {%0,%1,%2,%3}, [%4];\n"
                 : "=r"(b[0]), "=r"(b[1]), "=r"(b[2]), "=r"(b[3]) : "r"(addr));
}
DINL void mma16816(float (&d)[4], const uint32_t (&a)[4], uint32_t b0, uint32_t b1) {
    asm volatile(
        "mma.sync.aligned.m16n8k16.row.col.f32.f16.f16.f32 "
        "{%0,%1,%2,%3},{%4,%5,%6,%7},{%8,%9},{%0,%1,%2,%3};\n"
        : "+f"(d[0]), "+f"(d[1]), "+f"(d[2]), "+f"(d[3])
        : "r"(a[0]), "r"(a[1]), "r"(a[2]), "r"(a[3]), "r"(b0), "r"(b1));
}

DINL void cp16(uint32_t dst, const void* src) {
    asm volatile("cp.async.cg.shared.global [%0], [%1], 16;" :: "r"(dst), "l"(src));
}
#define CP_COMMIT() asm volatile("cp.async.commit_group;" ::: "memory")
#define CP_WAIT0()  asm volatile("cp.async.wait_group 0;" ::: "memory")

DINL uint32_t pack2(float a, float b) {
    __half2 h = __floats2half2_rn(a, b);
    return *reinterpret_cast<uint32_t*>(&h);
}

// 8 RBF values exp(-(s-i)^2), s = 3.5v+3.5, via two anchored ratio chains
// (4 MUFU). Each anchor is the largest value of its half; fp32 underflow of
// an anchor implies all chained values are below fp16-subnormal anyway.
DINL uint4 basis8v(float v) {
    float s = fmaf(3.5f, v, 3.5f);
    const float c = 0.13533528323661270f;      // e^{-2}
    float b0 = __expf(-s * s);
    float rl = __expf(fmaf(2.f, s, -1.f));     // e^{2s-1}
    float b1 = b0 * rl; rl *= c;
    float b2 = b1 * rl; rl *= c;
    float b3 = b2 * rl;
    float t  = s - 7.f;
    float b7 = __expf(-t * t);
    float rh = __expf(fmaf(-2.f, t, -1.f));    // e^{-2t-1}
    float b6 = b7 * rh; rh *= c;
    float b5 = b6 * rh; rh *= c;
    float b4 = b5 * rh;
    uint4 u;
    u.x = pack2(b0, b1); u.y = pack2(b2, b3);
    u.z = pack2(b4, b5); u.w = pack2(b6, b7);
    return u;
}

DINL float siluf(float v) { return __fdividef(v, 1.f + __expf(-v)); }

// ---------------- dummy (ncu capture-window alignment) ------------------------
__global__ void dummy_k() {}

// ---------------- weight packing --------------------------------------------
__global__ void prep_weights(const float* __restrict__ s1, const float* __restrict__ b1,
                             const float* __restrict__ s2, const float* __restrict__ b2) {
    int idx = blockIdx.x * 256 + threadIdx.x;
    const int N1 = 1792 * 384;
    const int N2 = 3456 * 208;
    if (idx < N1) {
        int k = idx / 384, o = idx % 384;
        float v = 0.f;
        if (k < 1568)       v = s1[o * 1568 + k];
        else if (k < 1764)  v = b1[o * 196 + (k - 1568)];
        g_W1[idx] = __float2half(v);
    } else if (idx < N1 + N2) {
        int j = idx - N1;
        int k = j / 208, o = j % 208;
        float v = 0.f;
        if (o < 196) v = (k < 3072) ? s2[o * 3072 + k] : b2[o * 384 + (k - 3072)];
        g_W2[j] = __float2half(v);
    }
}

// ---------------- stage 1 (full N=384 per CTA, BK=64) -------------------------
__global__ void __launch_bounds__(NT, 1)
kan_stage1(const float* __restrict__ x, const float* __restrict__ bias) {
    extern __shared__ char smem[];
    __half* Vs = (__half*)smem;

    const int tid  = threadIdx.x;
    const int lane = tid & 31, warp = tid >> 5;
    const int r0 = blockIdx.x * BM;
    const int bb = r0 / 768, c0 = r0 % 768;
    const float* xb = x + bb * (196 * 768) + c0;

    char* Ab[2] = { smem + S1_OFF_A0, smem + S1_OFF_A1 };
    const uint32_t Aa[2] = { smem_u32(Ab[0]), smem_u32(Ab[1]) };
    const uint32_t Ba[2] = { smem_u32(smem + S1_OFF_B0), smem_u32(smem + S1_OFF_B1) };

    // load V tile [128][196] fp16 (coalesced over c): 25088 = 49 x 512
    #pragma unroll 1
    for (int i = 0; i < 49; i++) {
        int idx = tid + i * NT;
        int j = idx >> 7, m = idx & 127;
        Vs[m * S1_RVH + j] = __float2half(xb[j * 768 + m]);
    }

    const int m_off  = (warp & 7) * 16;         // 8 m-groups of 16 rows
    const int n_base = (warp >> 3) * 192;       // 2 n-groups of 192 cols
    float acc[2][12][4];                        // h: n_base + h*96 + g*16
    #pragma unroll
    for (int h = 0; h < 2; h++)
        #pragma unroll
        for (int n = 0; n < 12; n++)
            #pragma unroll
            for (int q = 0; q < 4; q++) acc[h][n][q] = 0.f;

    __syncthreads();   // Vs ready

    // build A tile: 128 rows x 64 k; per thread 2 groups of 8 k
    auto buildA = [&](int kb, int d) {
        const int k0 = kb * BK;
        char* AsB = Ab[d];
        const int m = tid & 127, g0 = tid >> 7;
        #pragma unroll
        for (int it = 0; it < 2; it++) {
            const int g = g0 + it * 4;
            const int k = k0 + g * 8;
            uint4 u;
            if (k < S1_KS) {
                u = basis8v(__half2float(Vs[m * S1_RVH + (k >> 3)]));
            } else {
                const int j0 = k - S1_KS;
                float f[8];
                #pragma unroll
                for (int e = 0; e < 8; e++)
                    f[e] = (j0 + e < S1_DIN) ? siluf(__half2float(Vs[m * S1_RVH + j0 + e]))
                                             : 0.f;
                u.x = pack2(f[0], f[1]); u.y = pack2(f[2], f[3]);
                u.z = pack2(f[4], f[5]); u.w = pack2(f[6], f[7]);
            }
            *reinterpret_cast<uint4*>(AsB + m * S1_ROWA + g * 16) = u;
        }
    };
    // B tile: 64 rows x 384 halves -> 48 chunks/row, 3072 = 6 x 512
    auto loadB = [&](int kb, int d) {
        const __half* wsrc = g_W1 + kb * BK * S1_DOUT;
        uint32_t bdst = Ba[d];
        #pragma unroll
        for (int i = 0; i < 6; i++) {
            int idx = tid + i * NT;
            int kk = idx / 48, nv = idx % 48;
            cp16(bdst + kk * S1_ROWB + nv * 16, wsrc + kk * S1_DOUT + nv * 8);
        }
        CP_COMMIT();
    };

    buildA(0, 0);
    loadB(0, 0);

    for (int kc = 0; kc < S1_NK; kc++) {
        const int s = kc & 1;
        CP_WAIT0();
        __syncthreads();
        if (kc + 1 < S1_NK) loadB(kc + 1, s ^ 1);
        #pragma unroll
        for (int ks = 0; ks < 4; ks++) {
            uint32_t a[4];
            ldmA(a, Aa[s] + (uint32_t)((m_off + (lane & 15)) * S1_ROWA +
                                       (ks * 16 + (lane >> 4) * 8) * 2));
            #pragma unroll
            for (int h = 0; h < 2; h++) {
                #pragma unroll
                for (int g = 0; g < 6; g++) {
                    uint32_t b[4];
                    ldmBT(b, Ba[s] + (uint32_t)((ks * 16 + (lane & 15)) * S1_ROWB +
                                                (n_base + h * 96 + g * 16 +
                                                 ((lane >> 4) << 3)) * 2));
                    mma16816(acc[h][2 * g],     a, b[0], b[1]);
                    mma16816(acc[h][2 * g + 1], a, b[2], b[3]);
                }
            }
        }
        if (kc + 1 < S1_NK) buildA(kc + 1, s ^ 1);
    }

    // ---- epilogue: + bias, store h1 fp16 ----
    const int gq = lane >> 2, tq = lane & 3;
    #pragma unroll
    for (int h = 0; h < 2; h++) {
        #pragma unroll
        for (int nf = 0; nf < 12; nf++) {
            int o = n_base + h * 96 + nf * 8 + tq * 2;
            float b0 = bias[o], b1 = bias[o + 1];
            int m = m_off + gq;
            __half2 v0 = __floats2half2_rn(acc[h][nf][0] + b0, acc[h][nf][1] + b1);
            __half2 v1 = __floats2half2_rn(acc[h][nf][2] + b0, acc[h][nf][3] + b1);
            *reinterpret_cast<__half2*>(g_H1 + (size_t)(r0 + m) * 384 + o)     = v0;
            *reinterpret_cast<__half2*>(g_H1 + (size_t)(r0 + m + 8) * 384 + o) = v1;
        }
    }
}

// ---------------- stage 2 (N=208, BK=64) --------------------------------------
__global__ void __launch_bounds__(NT, 1)
kan_stage2(const float* __restrict__ x, const float* __restrict__ bias,
           float* __restrict__ out) {
    extern __shared__ char smem[];
    __half* Vs = (__half*)smem;

    const int tid  = threadIdx.x;
    const int lane = tid & 31, warp = tid >> 5;
    const int r0 = blockIdx.x * BM;
    const int bb = r0 / 768, c0 = r0 % 768;

    char* Ab[2] = { smem + S2_OFF_A0, smem + S2_OFF_A1 };
    const uint32_t Aa[2] = { smem_u32(Ab[0]), smem_u32(Ab[1]) };
    const uint32_t Ba[2] = { smem_u32(smem + S2_OFF_B0), smem_u32(smem + S2_OFF_B1) };

    // load h1 tile [128][384] fp16: 6144 x 16B chunks, 12 x 512
    #pragma unroll 1
    for (int i = 0; i < 12; i++) {
        int idx = tid + i * NT;
        int m = idx / 48, q = idx % 48;
        *reinterpret_cast<uint4*>((char*)Vs + m * (S2_RVH * 2) + q * 16) =
            *reinterpret_cast<const uint4*>(g_H1 + (size_t)(r0 + m) * 384 + q * 8);
    }

    const int m_off = (warp & 7) * 16;          // 8 m-groups of 16 rows
    const int hgrp  = warp >> 3;                // 0: cols 0..95 (6g), 1: 96..207 (7g)
    const int n_off = hgrp ? 96 : 0;
    const int ng    = hgrp ? 7 : 6;
    float acc[14][4];
    #pragma unroll
    for (int n = 0; n < 14; n++)
        #pragma unroll
        for (int q = 0; q < 4; q++) acc[n][q] = 0.f;

    __syncthreads();

    auto buildA = [&](int kb, int d) {
        const int k0 = kb * BK;
        char* AsB = Ab[d];
        const int m = tid & 127, g0 = tid >> 7;
        #pragma unroll
        for (int it = 0; it < 2; it++) {
            const int g = g0 + it * 4;
            const int k = k0 + g * 8;
            uint4 u;
            if (k < S2_KS) {
                u = basis8v(__half2float(Vs[m * S2_RVH + (k >> 3)]));
            } else {
                const int j0 = k - S2_KS;
                float f[8];
                #pragma unroll
                for (int e = 0; e < 8; e++)
                    f[e] = siluf(__half2float(Vs[m * S2_RVH + j0 + e]));
                u.x = pack2(f[0], f[1]); u.y = pack2(f[2], f[3]);
                u.z = pack2(f[4], f[5]); u.w = pack2(f[6], f[7]);
            }
            *reinterpret_cast<uint4*>(AsB + m * S2_ROWA + g * 16) = u;
        }
    };
    // B tile: 64 rows x 208 halves -> 26 chunks/row, 1664 chunks
    auto loadB = [&](int kb, int d) {
        const __half* wsrc = g_W2 + kb * BK * S2_NP;
        uint32_t bdst = Ba[d];
        #pragma unroll
        for (int i = 0; i < 4; i++) {
            int idx = tid + i * NT;
            if (idx < 1664) {
                int kk = idx / 26, nv = idx % 26;
                cp16(bdst + kk * S2_ROWB + nv * 16, wsrc + kk * S2_NP + nv * 8);
            }
        }
        CP_COMMIT();
    };

    buildA(0, 0);
    loadB(0, 0);

    for (int kc = 0; kc < S2_NK; kc++) {
        const int s = kc & 1;
        CP_WAIT0();
        __syncthreads();
        if (kc + 1 < S2_NK) loadB(kc + 1, s ^ 1);
        #pragma unroll
        for (int ks = 0; ks < 4; ks++) {
            uint32_t a[4];
            ldmA(a, Aa[s] + (uint32_t)((m_off + (lane & 15)) * S2_ROWA +
                                       (ks * 16 + (lane >> 4) * 8) * 2));
            #pragma unroll
            for (int g = 0; g < 7; g++) {
                if (g < ng) {
                    uint32_t b[4];
                    ldmBT(b, Ba[s] + (uint32_t)((ks * 16 + (lane & 15)) * S2_ROWB +
                                                (n_off + g * 16 +
                                                 ((lane >> 4) << 3)) * 2));
                    mma16816(acc[2 * g],     a, b[0], b[1]);
                    mma16816(acc[2 * g + 1], a, b[2], b[3]);
                }
            }
        }
        if (kc + 1 < S2_NK) buildA(kc + 1, s ^ 1);
    }

    // ---- epilogue: + bias + skip(x), store fp32 out[b, p, c] ----
    const int gq = lane >> 2, tq = lane & 3;
    #pragma unroll
    for (int nf = 0; nf < 14; nf++) {
        if (nf < 2 * ng) {
            int o = n_off + nf * 8 + tq * 2;
            if (o < 196) {
                int m = m_off + gq;
                float b0 = bias[o], b1 = bias[o + 1];
                size_t base0 = (size_t)bb * 150528 + (size_t)o * 768 + c0;
                size_t base1 = base0 + 768;   // o+1
                out[base0 + m]     = acc[nf][0] + b0 + x[base0 + m];
                out[base1 + m]     = acc[nf][1] + b1 + x[base1 + m];
                out[base0 + m + 8] = acc[nf][2] + b0 + x[base0 + m + 8];
                out[base1 + m + 8] = acc[nf][3] + b1 + x[base1 + m + 8];
            }
        }
    }
}

// ---------------- launch -----------------------------------------------------
extern "C" void kernel_launch(void* const* d_in, const int* in_sizes, int n_in,
                              void* d_out, int out_size) {
    (void)in_sizes; (void)n_in; (void)out_size;
    const float* x   = (const float*)d_in[0];
    const float* s1  = (const float*)d_in[1];
    const float* bw1 = (const float*)d_in[2];
    const float* bb1 = (const float*)d_in[3];
    const float* s2  = (const float*)d_in[4];
    const float* bw2 = (const float*)d_in[5];
    const float* bb2 = (const float*)d_in[6];
    float* out = (float*)d_out;

    cudaFuncSetAttribute(kan_stage1, cudaFuncAttributeMaxDynamicSharedMemorySize, S1_SMEM);
    cudaFuncSetAttribute(kan_stage2, cudaFuncAttributeMaxDynamicSharedMemorySize, S2_SMEM);

    const int total = 1792 * 384 + 3456 * 208;
    dummy_k<<<1, 32>>>();
    prep_weights<<<(total + 255) / 256, 256>>>(s1, bw1, s2, bw2);
    kan_stage1<<<dim3(384), NT, S1_SMEM>>>(x, bb1);
    kan_stage2<<<dim3(384), NT, S2_SMEM>>>(x, bb2, out);
    dummy_k<<<1, 32>>>();
}

// round 15
// speedup vs baseline: 1.3981x; 1.3981x over previous
#include <cuda_runtime.h>
#include <cuda_fp16.h>
#include <cstdint>

// ---------------------------------------------------------------------------
// KAN-Mixer token-mixing block, fused feature-expansion GEMMs (fp16 mma.sync).
// R15 = R11 champion + (a) buildA issued BEFORE MMA each K-block so the MUFU
// burst overlaps the HMMA burst, (b) 3-exp RBF basis (anchors i=0 and i=4,
// one shared geometric ratio chain).
//   stage1: f1 = [rbf(v) (1568), silu(v) (196)]  -> h1[r, 384]   (fp16)
//   stage2: f2 = [rbf(h1) (3072), silu(h1)(384)] -> out[b,p,c] = .. + x[b,p,c]
// ---------------------------------------------------------------------------

#define DINL __device__ __forceinline__

// ---------------- static scratch (no allocations allowed) -------------------
__device__ __align__(16) __half g_W1[1792 * 384];   // [k][o]
__device__ __align__(16) __half g_W2[3456 * 224];   // [k][o] (o padded)
__device__ __align__(16) __half g_H1[(size_t)49152 * 384];

// ---------------- tiling constants -------------------------------------------
constexpr int BM = 128;
constexpr int BK = 32;
constexpr int NT = 512;                         // threads per CTA

// stage1 (full N=384 per CTA)
constexpr int S1_DIN = 196, S1_KS = 1568, S1_NK = 56, S1_DOUT = 384;
constexpr int S1_ROWV = 197;                    // floats per V row
constexpr int S1_ROWB = 392;                    // halves per B row (384 + 8 pad)
constexpr int S1_OFF_A0 = BM * S1_ROWV * 4;             // 100864
constexpr int S1_OFF_A1 = S1_OFF_A0 + BM * 80;          // 111104
constexpr int S1_OFF_B0 = S1_OFF_A1 + BM * 80;          // 121344
constexpr int S1_OFF_B1 = S1_OFF_B0 + BK * S1_ROWB * 2; // 146432
constexpr int S1_SMEM   = S1_OFF_B1 + BK * S1_ROWB * 2; // 171520

// stage2
constexpr int S2_DIN = 384, S2_KS = 3072, S2_NK = 108, S2_NP = 224;
constexpr int S2_ROWV = 392;                    // halves per V row
constexpr int S2_OFF_A0 = BM * S2_ROWV * 2;             // 100352
constexpr int S2_OFF_A1 = S2_OFF_A0 + BM * 80;          // 110592
constexpr int S2_OFF_B0 = S2_OFF_A1 + BM * 80;          // 120832
constexpr int S2_OFF_B1 = S2_OFF_B0 + BK * 464;         // 135680
constexpr int S2_SMEM   = S2_OFF_B1 + BK * 464;         // 150528

// ---------------- small helpers ---------------------------------------------
DINL uint32_t smem_u32(const void* p) {
    return (uint32_t)__cvta_generic_to_shared(p);
}

DINL void ldmA(uint32_t (&a)[4], uint32_t addr) {
    asm volatile("ldmatrix.sync.aligned.m8n8.x4.shared.b16 {%0,%1,%2,%3}, [%4];\n"
                 : "=r"(a[0]), "=r"(a[1]), "=r"(a[2]), "=r"(a[3]) : "r"(addr));
}
DINL void ldmBT(uint32_t (&b)[4], uint32_t addr) {
    asm volatile("ldmatrix.sync.aligned.m8n8.x4.trans.shared.b16 {%0,%1,%2,%3}, [%4];\n"
                 : "=r"(b[0]), "=r"(b[1]), "=r"(b[2]), "=r"(b[3]) : "r"(addr));
}
DINL void mma16816(float (&d)[4], const uint32_t (&a)[4], uint32_t b0, uint32_t b1) {
    asm volatile(
        "mma.sync.aligned.m16n8k16.row.col.f32.f16.f16.f32 "
        "{%0,%1,%2,%3},{%4,%5,%6,%7},{%8,%9},{%0,%1,%2,%3};\n"
        : "+f"(d[0]), "+f"(d[1]), "+f"(d[2]), "+f"(d[3])
        : "r"(a[0]), "r"(a[1]), "r"(a[2]), "r"(a[3]), "r"(b0), "r"(b1));
}

DINL void cp16(uint32_t dst, const void* src) {
    asm volatile("cp.async.cg.shared.global [%0], [%1], 16;" :: "r"(dst), "l"(src));
}
#define CP_COMMIT() asm volatile("cp.async.commit_group;" ::: "memory")
#define CP_WAIT0()  asm volatile("cp.async.wait_group 0;" ::: "memory")

DINL uint32_t pack2(float a, float b) {
    __half2 h = __floats2half2_rn(a, b);
    return *reinterpret_cast<uint32_t*>(&h);
}

// 8 RBF values exp(-(s-i)^2), s = 3.5v+3.5, with THREE exp calls:
// anchors b0 = e^{-s^2} and b4 = e^{-(s-4)^2}, plus one running ratio
// r_i = e^{2s-2i-1} (consecutive-basis ratio, geometric in e^{-2}) shared by
// both up-chains (b0->b1..b3 and b4->b5..b7).
// Underflow audit (fp32 FTZ, min normal e^{-87.3}):
//  - b0 underflows only for |s|>9.34, where b1..b3 are < fp16-subnormal anyway.
//  - b4 underflows only for s>13.3 or s<-5.3, where b5..b7 are < fp16-subnormal.
// Same overflow exposure as the previous 4-exp chain (needs |v|>11.8).
DINL uint4 basis8v(float v) {
    float s = fmaf(3.5f, v, 3.5f);
    const float c = 0.13533528323661270f;      // e^{-2}
    float b0 = __expf(-s * s);
    float t  = s - 4.f;
    float b4 = __expf(-t * t);
    float r  = __expf(fmaf(2.f, s, -1.f));     // e^{2s-1}
    float b1 = b0 * r; r *= c;                 // r -> e^{2s-3}
    float b2 = b1 * r; r *= c;                 // r -> e^{2s-5}
    float b3 = b2 * r; r *= c;                 // r -> e^{2s-7}
    r *= c;                                    // r -> e^{2s-9}  (b4->b5 ratio)
    float b5 = b4 * r; r *= c;                 // r -> e^{2s-11}
    float b6 = b5 * r; r *= c;                 // r -> e^{2s-13}
    float b7 = b6 * r;
    uint4 u;
    u.x = pack2(b0, b1); u.y = pack2(b2, b3);
    u.z = pack2(b4, b5); u.w = pack2(b6, b7);
    return u;
}

DINL float siluf(float v) { return __fdividef(v, 1.f + __expf(-v)); }

// ---------------- dummy (ncu capture-window alignment) ------------------------
__global__ void dummy_k() {}

// ---------------- weight packing --------------------------------------------
__global__ void prep_weights(const float* __restrict__ s1, const float* __restrict__ b1,
                             const float* __restrict__ s2, const float* __restrict__ b2) {
    int idx = blockIdx.x * 256 + threadIdx.x;
    const int N1 = 1792 * 384;
    const int N2 = 3456 * 224;
    if (idx < N1) {
        int k = idx / 384, o = idx % 384;
        float v = 0.f;
        if (k < 1568)       v = s1[o * 1568 + k];
        else if (k < 1764)  v = b1[o * 196 + (k - 1568)];
        g_W1[idx] = __float2half(v);
    } else if (idx < N1 + N2) {
        int j = idx - N1;
        int k = j / 224, o = j % 224;
        float v = 0.f;
        if (o < 196) v = (k < 3072) ? s2[o * 3072 + k] : b2[o * 384 + (k - 3072)];
        g_W2[j] = __float2half(v);
    }
}

// ---------------- stage 1 (full N=384 per CTA, 16 warps) ----------------------
__global__ void __launch_bounds__(NT, 1)
kan_stage1(const float* __restrict__ x, const float* __restrict__ bias) {
    extern __shared__ char smem[];
    float* Vs = (float*)smem;

    const int tid  = threadIdx.x;
    const int lane = tid & 31, warp = tid >> 5;
    const int r0 = blockIdx.x * BM;
    const int bb = r0 / 768, c0 = r0 % 768;
    const float* xb = x + bb * (196 * 768) + c0;

    char* Ab[2] = { smem + S1_OFF_A0, smem + S1_OFF_A1 };
    const uint32_t Aa[2] = { smem_u32(Ab[0]), smem_u32(Ab[1]) };
    const uint32_t Ba[2] = { smem_u32(smem + S1_OFF_B0), smem_u32(smem + S1_OFF_B1) };

    // load V tile [128][196] (coalesced over c): 25088 floats, 49 x 512
    #pragma unroll 1
    for (int i = 0; i < (BM * S1_DIN) / NT; i++) {
        int idx = tid + i * NT;
        int j = idx >> 7, m = idx & 127;
        Vs[m * S1_ROWV + j] = xb[j * 768 + m];
    }

    const int m_off  = (warp & 7) * 16;         // 8 m-groups of 16 rows
    const int n_base = (warp >> 3) * 192;       // 2 n-groups of 192 cols
    float acc[2][12][4];                        // h: n_base + h*96 + g*16
    #pragma unroll
    for (int h = 0; h < 2; h++)
        #pragma unroll
        for (int n = 0; n < 12; n++)
            #pragma unroll
            for (int q = 0; q < 4; q++) acc[h][n][q] = 0.f;

    __syncthreads();   // Vs ready

    auto buildA = [&](int kb, int d) {
        const int k0 = kb * BK;
        char* AsB = Ab[d];
        if (k0 < S1_KS) {
            int j0 = k0 >> 3;
            // 512 basis calls, one per thread
            int m = tid & 127, jj = tid >> 7;
            float v = Vs[m * S1_ROWV + j0 + jj];
            *reinterpret_cast<uint4*>(AsB + m * 80 + jj * 16) = basis8v(v);
        } else {
            int j0 = k0 - S1_KS;
            #pragma unroll
            for (int it = 0; it < 4; it++) {
                int t = tid + it * NT;
                int m = t >> 4, q = t & 15;
                int j = j0 + q * 2;
                float f0 = (j     < S1_DIN) ? siluf(Vs[m * S1_ROWV + j])     : 0.f;
                float f1 = (j + 1 < S1_DIN) ? siluf(Vs[m * S1_ROWV + j + 1]) : 0.f;
                *reinterpret_cast<uint32_t*>(AsB + m * 80 + q * 4) = pack2(f0, f1);
            }
        }
    };
    // B tile: 32 rows x 384 halves (stride 392 halves), 1536 x 16B chunks
    auto loadB = [&](int kb, int d) {
        const __half* wsrc = g_W1 + kb * BK * S1_DOUT;
        uint32_t bdst = Ba[d];
        #pragma unroll
        for (int i = 0; i < 3; i++) {
            int idx = tid + i * NT;
            int kk = idx / 48, nv = idx % 48;
            cp16(bdst + kk * (S1_ROWB * 2) + nv * 16, wsrc + kk * S1_DOUT + nv * 8);
        }
        CP_COMMIT();
    };

    buildA(0, 0);
    loadB(0, 0);

    for (int kc = 0; kc < S1_NK; kc++) {
        const int s = kc & 1;
        CP_WAIT0();
        __syncthreads();
        if (kc + 1 < S1_NK) {
            loadB(kc + 1, s ^ 1);
            buildA(kc + 1, s ^ 1);    // MUFU burst issues first, overlaps MMA below
        }
        #pragma unroll
        for (int ks = 0; ks < 2; ks++) {
            uint32_t a[4];
            {
                uint32_t addr = Aa[s] + (uint32_t)((m_off + (lane & 15)) * 80 +
                                                   (ks * 16 + (lane >> 4) * 8) * 2);
                ldmA(a, addr);
            }
            #pragma unroll
            for (int h = 0; h < 2; h++) {
                #pragma unroll
                for (int g = 0; g < 6; g++) {
                    uint32_t b[4];
                    uint32_t addr = Ba[s] +
                        (uint32_t)((ks * 16 + (lane & 15)) * (S1_ROWB * 2) +
                                   (n_base + h * 96 + g * 16 + ((lane >> 4) << 3)) * 2);
                    ldmBT(b, addr);
                    mma16816(acc[h][2 * g],     a, b[0], b[1]);
                    mma16816(acc[h][2 * g + 1], a, b[2], b[3]);
                }
            }
        }
    }

    // ---- epilogue: + bias, store h1 fp16 ----
    const int gq = lane >> 2, tq = lane & 3;
    #pragma unroll
    for (int h = 0; h < 2; h++) {
        #pragma unroll
        for (int nf = 0; nf < 12; nf++) {
            int o = n_base + h * 96 + nf * 8 + tq * 2;
            float b0 = bias[o], b1 = bias[o + 1];
            int m = m_off + gq;
            __half2 v0 = __floats2half2_rn(acc[h][nf][0] + b0, acc[h][nf][1] + b1);
            __half2 v1 = __floats2half2_rn(acc[h][nf][2] + b0, acc[h][nf][3] + b1);
            *reinterpret_cast<__half2*>(g_H1 + (size_t)(r0 + m) * 384 + o)     = v0;
            *reinterpret_cast<__half2*>(g_H1 + (size_t)(r0 + m + 8) * 384 + o) = v1;
        }
    }
}

// ---------------- stage 2 (16 warps) ------------------------------------------
__global__ void __launch_bounds__(NT, 1)
kan_stage2(const float* __restrict__ x, const float* __restrict__ bias,
           float* __restrict__ out) {
    extern __shared__ char smem[];
    __half* Vs = (__half*)smem;

    const int tid  = threadIdx.x;
    const int lane = tid & 31, warp = tid >> 5;
    const int r0 = blockIdx.x * BM;
    const int bb = r0 / 768, c0 = r0 % 768;

    char* Ab[2] = { smem + S2_OFF_A0, smem + S2_OFF_A1 };
    const uint32_t Aa[2] = { smem_u32(Ab[0]), smem_u32(Ab[1]) };
    const uint32_t Ba[2] = { smem_u32(smem + S2_OFF_B0), smem_u32(smem + S2_OFF_B1) };

    // load h1 tile [128][384] fp16: 6144 x 16B chunks, 12 x 512
    #pragma unroll 1
    for (int i = 0; i < 12; i++) {
        int idx = tid + i * NT;
        int m = idx / 48, q = idx % 48;
        *reinterpret_cast<uint4*>((char*)Vs + m * 784 + q * 16) =
            *reinterpret_cast<const uint4*>(g_H1 + (size_t)(r0 + m) * 384 + q * 8);
    }

    const int m_off = (warp & 7) * 16;          // 8 m-groups of 16 rows
    const int n_off = (warp >> 3) * 112;        // 2 n-groups of 112 cols
    float acc[14][4];
    #pragma unroll
    for (int n = 0; n < 14; n++)
        #pragma unroll
        for (int q = 0; q < 4; q++) acc[n][q] = 0.f;

    __syncthreads();

    auto buildA = [&](int kb, int d) {
        const int k0 = kb * BK;
        char* AsB = Ab[d];
        if (k0 < S2_KS) {
            int j0 = k0 >> 3;
            int m = tid & 127, jj = tid >> 7;
            float v = __half2float(Vs[m * S2_ROWV + j0 + jj]);
            *reinterpret_cast<uint4*>(AsB + m * 80 + jj * 16) = basis8v(v);
        } else {
            int j0 = k0 - S2_KS;
            #pragma unroll
            for (int it = 0; it < 4; it++) {
                int t = tid + it * NT;
                int m = t >> 4, q = t & 15;
                int j = j0 + q * 2;
                float f0 = siluf(__half2float(Vs[m * S2_ROWV + j]));
                float f1 = siluf(__half2float(Vs[m * S2_ROWV + j + 1]));
                *reinterpret_cast<uint32_t*>(AsB + m * 80 + q * 4) = pack2(f0, f1);
            }
        }
    };
    auto loadB = [&](int kb, int d) {
        const __half* wsrc = g_W2 + kb * BK * S2_NP;
        uint32_t bdst = Ba[d];
        #pragma unroll
        for (int i = 0; i < 2; i++) {
            int idx = tid + i * NT;
            if (idx < 896) {
                int kk = idx / 28, nv = idx % 28;
                cp16(bdst + kk * 464 + nv * 16, wsrc + kk * S2_NP + nv * 8);
            }
        }
        CP_COMMIT();
    };

    buildA(0, 0);
    loadB(0, 0);

    for (int kc = 0; kc < S2_NK; kc++) {
        const int s = kc & 1;
        CP_WAIT0();
        __syncthreads();
        if (kc + 1 < S2_NK) {
            loadB(kc + 1, s ^ 1);
            buildA(kc + 1, s ^ 1);    // MUFU burst issues first, overlaps MMA below
        }
        #pragma unroll
        for (int ks = 0; ks < 2; ks++) {
            uint32_t a[4];
            {
                uint32_t addr = Aa[s] + (uint32_t)((m_off + (lane & 15)) * 80 +
                                                   (ks * 16 + (lane >> 4) * 8) * 2);
                ldmA(a, addr);
            }
            #pragma unroll
            for (int g = 0; g < 7; g++) {
                uint32_t b[4];
                uint32_t addr = Ba[s] + (uint32_t)((ks * 16 + (lane & 15)) * 464 +
                                                   (n_off + g * 16 + ((lane >> 4) << 3)) * 2);
                ldmBT(b, addr);
                mma16816(acc[2 * g],     a, b[0], b[1]);
                mma16816(acc[2 * g + 1], a, b[2], b[3]);
            }
        }
    }

    // ---- epilogue: + bias + skip(x), store fp32 out[b, p, c] ----
    const int gq = lane >> 2, tq = lane & 3;
    #pragma unroll
    for (int nf = 0; nf < 14; nf++) {
        int o = n_off + nf * 8 + tq * 2;
        if (o < 196) {
            int m = m_off + gq;
            float b0 = bias[o], b1 = bias[o + 1];
            size_t base0 = (size_t)bb * 150528 + (size_t)o * 768 + c0;
            size_t base1 = base0 + 768;   // o+1
            out[base0 + m]     = acc[nf][0] + b0 + x[base0 + m];
            out[base1 + m]     = acc[nf][1] + b1 + x[base1 + m];
            out[base0 + m + 8] = acc[nf][2] + b0 + x[base0 + m + 8];
            out[base1 + m + 8] = acc[nf][3] + b1 + x[base1 + m + 8];
        }
    }
}

// ---------------- launch -----------------------------------------------------
extern "C" void kernel_launch(void* const* d_in, const int* in_sizes, int n_in,
                              void* d_out, int out_size) {
    (void)in_sizes; (void)n_in; (void)out_size;
    const float* x   = (const float*)d_in[0];
    const float* s1  = (const float*)d_in[1];
    const float* bw1 = (const float*)d_in[2];
    const float* bb1 = (const float*)d_in[3];
    const float* s2  = (const float*)d_in[4];
    const float* bw2 = (const float*)d_in[5];
    const float* bb2 = (const float*)d_in[6];
    float* out = (float*)d_out;

    cudaFuncSetAttribute(kan_stage1, cudaFuncAttributeMaxDynamicSharedMemorySize, S1_SMEM);
    cudaFuncSetAttribute(kan_stage2, cudaFuncAttributeMaxDynamicSharedMemorySize, S2_SMEM);

    const int total = 1792 * 384 + 3456 * 224;
    dummy_k<<<1, 32>>>();
    prep_weights<<<(total + 255) / 256, 256>>>(s1, bw1, s2, bw2);
    kan_stage1<<<dim3(384), NT, S1_SMEM>>>(x, bb1);
    kan_stage2<<<dim3(384), NT, S2_SMEM>>>(x, bb2, out);
    dummy_k<<<1, 32>>>();
}